// round 2
// baseline (speedup 1.0000x reference)
#include <cuda_runtime.h>
#include <cstdint>

#define NN 10000
#define KK 32
#define FF 128
#define NR 300

typedef unsigned long long ull;

// scratch (no cudaMalloc allowed)
__device__ float g_pre[NN * FF];
__device__ float g_conv[NN * FF];

__device__ __forceinline__ ull pk2(float lo, float hi) {
    ull r;
    asm("mov.b64 %0, {%1, %2};" : "=l"(r)
        : "r"(__float_as_uint(lo)), "r"(__float_as_uint(hi)));
    return r;
}
__device__ __forceinline__ ull ffma2(ull a, ull b, ull c) {
    ull d;
    asm("fma.rn.f32x2 %0, %1, %2, %3;" : "=l"(d) : "l"(a), "l"(b), "l"(c));
    return d;
}
__device__ __forceinline__ float lo2(ull v) { return __uint_as_float((unsigned)v); }
__device__ __forceinline__ float hi2(ull v) { return __uint_as_float((unsigned)(v >> 32)); }

// shifted softplus: softplus(x) - ln2 = max(x,0) + log(0.5 + 0.5*exp(-|x|))
__device__ __forceinline__ float sspf(float x) {
    return fmaxf(x, 0.0f) + __logf(fmaf(0.5f, __expf(-fabsf(x)), 0.5f));
}

// ---------------------------------------------------------------------------
// pre = atomic @ W_pre + b_pre
// ---------------------------------------------------------------------------
__global__ void pre_kernel(const float* __restrict__ atomic,
                           const float* __restrict__ W,
                           const float* __restrict__ b) {
    __shared__ float row[FF];
    int i = blockIdx.x, f = threadIdx.x;
    row[f] = atomic[i * FF + f];
    __syncthreads();
    float acc = b[f];
#pragma unroll 8
    for (int c = 0; c < FF; c++) acc = fmaf(row[c], W[c * FF + f], acc);
    g_pre[i * FF + f] = acc;
}

// ---------------------------------------------------------------------------
// fused per-node: distances -> rbf -> ssp(rbf@Wc1) -> ssp(.@Wc2) -> masked
// reduce with gathered pre -> g_conv
// thread map: f2 = tid&63 owns feature pair (2*f2, 2*f2+1); kh = tid>>6 owns
// k-half [kh*16, kh*16+16). 64-bit f32x2 packed accumulators (16 per thread).
// rbf/h1 are stored lane-DUPLICATED in shared so LDS.128 yields two packed
// broadcast operands with no pack instructions in the inner loop.
// ---------------------------------------------------------------------------
__global__ void __launch_bounds__(128, 2)
conv_kernel(const float* __restrict__ xyz, const float* __restrict__ emask,
            const int* __restrict__ src, const float* __restrict__ Wc1,
            const float* __restrict__ Wc2, const float* __restrict__ centers) {
    extern __shared__ float sm[];
    float* rbfd = sm;              // [32][600]  (each rbf value duplicated)
    float* h1d  = sm + 32 * 600;   // [32][256]  (each h1 value duplicated)
    __shared__ float d_sh[KK];
    __shared__ int   s_sh[KK];
    __shared__ float m_sh[KK];
    __shared__ ull   convp[128];

    const int i   = blockIdx.x;
    const int tid = threadIdx.x;
    const int f2  = tid & 63;
    const int kh  = tid >> 6;

    if (tid < KK) {
        int s = src[i * KK + tid];
        s_sh[tid] = s;
        float dx = xyz[3 * s + 0] - xyz[3 * i + 0];
        float dy = xyz[3 * s + 1] - xyz[3 * i + 1];
        float dz = xyz[3 * s + 2] - xyz[3 * i + 2];
        d_sh[tid] = sqrtf(dx * dx + dy * dy + dz * dz);
        m_sh[tid] = emask[i * KK + tid];
    }
    __syncthreads();

    // rbf: 32*300 values, duplicated into float2
    for (int idx = tid; idx < KK * NR; idx += 128) {
        int k = idx / NR;
        int r = idx - k * NR;
        float t = d_sh[k] - centers[r];
        float v = __expf(-10.0f * t * t);
        ((float2*)(rbfd + k * 600))[r] = make_float2(v, v);
    }
    __syncthreads();

    // ---- GEMM1: h1 = ssp(rbf @ Wc1) ----
    ull acc[16];
#pragma unroll
    for (int k = 0; k < 16; k++) acc[k] = 0ull;

    const ull* Wp = (const ull*)Wc1;                       // [300][64] f32-pairs
    const float4* R = (const float4*)(rbfd + kh * 16 * 600);  // rows of 150 f4

    ull w00 = Wp[0 * 64 + f2], w01 = Wp[1 * 64 + f2];
    ull w10 = Wp[2 * 64 + f2], w11 = Wp[3 * 64 + f2];
#pragma unroll 1
    for (int r2 = 0; r2 < 150; r2 += 2) {
        int nr = (r2 + 2 < 150) ? (2 * (r2 + 2)) : 0;   // prefetch next group
        ull nw00 = Wp[(nr + 0) * 64 + f2];
        ull nw01 = Wp[(nr + 1) * 64 + f2];
        ull nw10 = Wp[(nr + 2) * 64 + f2];
        ull nw11 = Wp[(nr + 3) * 64 + f2];
#pragma unroll
        for (int k = 0; k < 16; k++) {
            float4 a = R[k * 150 + r2];
            float4 b = R[k * 150 + r2 + 1];
            acc[k] = ffma2(pk2(a.x, a.y), w00, acc[k]);
            acc[k] = ffma2(pk2(a.z, a.w), w01, acc[k]);
            acc[k] = ffma2(pk2(b.x, b.y), w10, acc[k]);
            acc[k] = ffma2(pk2(b.z, b.w), w11, acc[k]);
        }
        w00 = nw00; w01 = nw01; w10 = nw10; w11 = nw11;
    }

    // ssp + write h1 (duplicated)
#pragma unroll
    for (int k = 0; k < 16; k++) {
        float lo = sspf(lo2(acc[k]));
        float hi = sspf(hi2(acc[k]));
        float2* hp = (float2*)(h1d + (kh * 16 + k) * 256);
        hp[2 * f2 + 0] = make_float2(lo, lo);
        hp[2 * f2 + 1] = make_float2(hi, hi);
    }
    __syncthreads();

    // ---- GEMM2: filters = ssp(h1 @ Wc2) ----
#pragma unroll
    for (int k = 0; k < 16; k++) acc[k] = 0ull;
    const ull* W2p = (const ull*)Wc2;                      // [128][64] f32-pairs
    const float4* H = (const float4*)(h1d + kh * 16 * 256);  // rows of 64 f4

    ull v00 = W2p[0 * 64 + f2], v01 = W2p[1 * 64 + f2];
    ull v10 = W2p[2 * 64 + f2], v11 = W2p[3 * 64 + f2];
#pragma unroll 1
    for (int c2 = 0; c2 < 64; c2 += 2) {
        int nc = (c2 + 2 < 64) ? (2 * (c2 + 2)) : 0;
        ull nv00 = W2p[(nc + 0) * 64 + f2];
        ull nv01 = W2p[(nc + 1) * 64 + f2];
        ull nv10 = W2p[(nc + 2) * 64 + f2];
        ull nv11 = W2p[(nc + 3) * 64 + f2];
#pragma unroll
        for (int k = 0; k < 16; k++) {
            float4 a = H[k * 64 + c2];
            float4 b = H[k * 64 + c2 + 1];
            acc[k] = ffma2(pk2(a.x, a.y), v00, acc[k]);
            acc[k] = ffma2(pk2(a.z, a.w), v01, acc[k]);
            acc[k] = ffma2(pk2(b.x, b.y), v10, acc[k]);
            acc[k] = ffma2(pk2(b.z, b.w), v11, acc[k]);
        }
        v00 = nv00; v01 = nv01; v10 = nv10; v11 = nv11;
    }

    // ---- conv reduce: sum_k ssp(filters) * pre[src] * mask ----
    const ull* P = (const ull*)g_pre;
    ull conv = 0ull;
#pragma unroll
    for (int k = 0; k < 16; k++) {
        int kk = kh * 16 + k;
        float flo = sspf(lo2(acc[k]));
        float fhi = sspf(hi2(acc[k]));
        float m = m_sh[kk];
        ull pr = P[s_sh[kk] * 64 + f2];
        float plo = lo2(pr) * m;
        float phi = hi2(pr) * m;
        conv = ffma2(pk2(flo, fhi), pk2(plo, phi), conv);
    }
    convp[kh * 64 + f2] = conv;
    __syncthreads();
    if (tid < 64) {
        ull a = convp[tid];
        ull b = convp[64 + tid];
        ((float2*)(g_conv + i * FF))[tid] =
            make_float2(lo2(a) + lo2(b), hi2(a) + hi2(b));
    }
}

// ---------------------------------------------------------------------------
// out = atomic + ssp(conv @ W1 + b1) @ W2 + b2
// ---------------------------------------------------------------------------
__global__ void post_kernel(const float* __restrict__ atomic,
                            const float* __restrict__ W1,
                            const float* __restrict__ b1,
                            const float* __restrict__ W2,
                            const float* __restrict__ b2,
                            float* __restrict__ out) {
    __shared__ float row[FF];
    __shared__ float tt[FF];
    int i = blockIdx.x, f = threadIdx.x;
    row[f] = g_conv[i * FF + f];
    __syncthreads();
    float acc = b1[f];
#pragma unroll 8
    for (int c = 0; c < FF; c++) acc = fmaf(row[c], W1[c * FF + f], acc);
    tt[f] = sspf(acc);
    __syncthreads();
    float acc2 = b2[f];
#pragma unroll 8
    for (int c = 0; c < FF; c++) acc2 = fmaf(tt[c], W2[c * FF + f], acc2);
    out[i * FF + f] = atomic[i * FF + f] + acc2;
}

// ---------------------------------------------------------------------------
extern "C" void kernel_launch(void* const* d_in, const int* in_sizes, int n_in,
                              void* d_out, int out_size) {
    const float* xyz     = (const float*)d_in[0];
    const float* atomic  = (const float*)d_in[1];
    const float* emask   = (const float*)d_in[2];
    const int*   src     = (const int*)  d_in[3];
    const float* W_pre   = (const float*)d_in[4];
    const float* b_pre   = (const float*)d_in[5];
    const float* W_cf1   = (const float*)d_in[6];
    const float* W_cf2   = (const float*)d_in[7];
    const float* W_post1 = (const float*)d_in[8];
    const float* b_post1 = (const float*)d_in[9];
    const float* W_post2 = (const float*)d_in[10];
    const float* b_post2 = (const float*)d_in[11];
    const float* centers = (const float*)d_in[12];
    float* out = (float*)d_out;

    const int smem = (32 * 600 + 32 * 256) * 4;  // 109568 bytes
    cudaFuncSetAttribute(conv_kernel,
                         cudaFuncAttributeMaxDynamicSharedMemorySize, smem);

    pre_kernel<<<NN, FF>>>(atomic, W_pre, b_pre);
    conv_kernel<<<NN, 128, smem>>>(xyz, emask, src, W_cf1, W_cf2, centers);
    post_kernel<<<NN, FF>>>(atomic, W_post1, b_post1, W_post2, b_post2, out);
}